// round 16
// baseline (speedup 1.0000x reference)
#include <cuda_runtime.h>
#include <cstdint>

typedef unsigned long long ull;

#define T_STEPS  512
#define BATCH    64
#define EDIM     300
#define HDIM     512
#define BH       (BATCH * HDIM)
#define NBLK     128
#define NTHREADS 256

// strides in float4 units
#define WIH0_S   96     // 75 real + zero pad (3 chunks x 32 f4)
#define WH_S     128    // exact (4 chunks x 32 f4)
#define TILE_S   33     // 32 real + 1 pad
#define TILE_F4  (64 * TILE_S)   // 2112 f4 per buffer

// -------------------- persistent device scratch (no allocations) -----------
__device__ float g_h1[(size_t)T_STEPS * BH];   // layer-0 hidden, all t
__device__ float g_h2[(size_t)T_STEPS * BH];   // layer-1 hidden, all t
__device__ float g_zero[BH];                   // never written: stays 0
__device__ float g_pooled[T_STEPS * HDIM];     // mean over batch of h2
__device__ unsigned g_flags[NBLK];             // per-CTA absolute step flags (reset at end)
__device__ unsigned g_release;                 // aggregator release word (reset at end)

// -------------------- helpers ---------------------------------------------
__device__ __forceinline__ void fma2(ull& acc, ull a, ull b) {
    asm volatile("fma.rn.f32x2 %0, %1, %2, %0;" : "+l"(acc) : "l"(a), "l"(b));
}
__device__ __forceinline__ float hsum2(ull v) {
    return __uint_as_float((unsigned)v) + __uint_as_float((unsigned)(v >> 32));
}
__device__ __forceinline__ float sigf(float x) { return 1.0f / (1.0f + expf(-x)); }

__device__ __forceinline__ float redq(ull a) {
    float f = hsum2(a);
    f += __shfl_xor_sync(0xffffffffu, f, 1);
    f += __shfl_xor_sync(0xffffffffu, f, 2);
    f += __shfl_xor_sync(0xffffffffu, f, 4);
    return f;
}

// cp.async: 16B GMEM->SMEM, zero-fill beyond src_sz bytes
__device__ __forceinline__ void cp16(uint32_t dst, const void* src, unsigned src_sz) {
    asm volatile("cp.async.cg.shared.global [%0], [%1], 16, %2;"
                 :: "r"(dst), "l"(src), "r"(src_sz) : "memory");
}
__device__ __forceinline__ void cp_commit() {
    asm volatile("cp.async.commit_group;" ::: "memory");
}
__device__ __forceinline__ void cp_wait0() {
    asm volatile("cp.async.wait_group 0;" ::: "memory");
}

// ---- 8 batches x 3 rows, 128-wide chunk: thread K-slice f4 {kq,+8,+16,+24} --
__device__ __forceinline__ void mac3x8(const ulonglong2* __restrict__ t,
    const ulonglong2* __restrict__ w0, const ulonglong2* __restrict__ w1,
    const ulonglong2* __restrict__ w2,
    ull A0[8], ull A1[8], ull A2[8])
{
#pragma unroll
    for (int i = 0; i < 4; i++) {
        const int o = 8 * i;
        ulonglong2 v0 = w0[o], v1 = w1[o], v2 = w2[o];
#pragma unroll
        for (int half = 0; half < 2; half++) {
            const int hb = half * 4;
            ulonglong2 h0 = t[(hb + 0) * TILE_S + o];
            ulonglong2 h1 = t[(hb + 1) * TILE_S + o];
            ulonglong2 h2 = t[(hb + 2) * TILE_S + o];
            ulonglong2 h3 = t[(hb + 3) * TILE_S + o];
            fma2(A0[hb+0], h0.x, v0.x); fma2(A0[hb+0], h0.y, v0.y);
            fma2(A0[hb+1], h1.x, v0.x); fma2(A0[hb+1], h1.y, v0.y);
            fma2(A0[hb+2], h2.x, v0.x); fma2(A0[hb+2], h2.y, v0.y);
            fma2(A0[hb+3], h3.x, v0.x); fma2(A0[hb+3], h3.y, v0.y);
            fma2(A1[hb+0], h0.x, v1.x); fma2(A1[hb+0], h0.y, v1.y);
            fma2(A1[hb+1], h1.x, v1.x); fma2(A1[hb+1], h1.y, v1.y);
            fma2(A1[hb+2], h2.x, v1.x); fma2(A1[hb+2], h2.y, v1.y);
            fma2(A1[hb+3], h3.x, v1.x); fma2(A1[hb+3], h3.y, v1.y);
            fma2(A2[hb+0], h0.x, v2.x); fma2(A2[hb+0], h0.y, v2.y);
            fma2(A2[hb+1], h1.x, v2.x); fma2(A2[hb+1], h1.y, v2.y);
            fma2(A2[hb+2], h2.x, v2.x); fma2(A2[hb+2], h2.y, v2.y);
            fma2(A2[hb+3], h3.x, v2.x); fma2(A2[hb+3], h3.y, v2.y);
        }
    }
}

__device__ __forceinline__ void stage128(float4* dst, const float* W, int j0, int tid) {
    for (int idx = tid; idx < 12 * WH_S; idx += NTHREADS) {
        int m = idx >> 7, f4 = idx & 127;
        int g = m >> 2, u = m & 3;
        dst[idx] = reinterpret_cast<const float4*>(W + (size_t)(g * HDIM + j0 + u) * HDIM)[f4];
    }
}

// =====  fused 2-layer GRU: lag-2 layer1, aggregator barrier, cp.async  ======
// Thread = (bg in 8, jj in 4, kq in 8). Chunk = 128 K-floats (32 f4/row).
// step s: layer0 @ t=s (s<512); layer1 @ t=s-2 (s>=2).
// pre-wait: L0 emb-proj (3 chunks) + L1 input-proj from h1[s-2] (4 chunks).
// post-wait: L0 rec from h1[s-1] (4) + L1 rec from h2[s-3] (4).
__global__ void __launch_bounds__(NTHREADS, 1)
gru_fused(const int* __restrict__ texts, const float* __restrict__ emb,
          const float* __restrict__ Wih0, const float* __restrict__ Whh0,
          const float* __restrict__ bih0, const float* __restrict__ bhh0,
          const float* __restrict__ Wih1, const float* __restrict__ Whh1,
          const float* __restrict__ bih1, const float* __restrict__ bhh1)
{
    extern __shared__ float4 smem[];
    float4* w_ih0 = smem;                               // 12*96  = 1152 f4
    float4* w_hh0 = smem + 12 * WIH0_S;                 // 12*128 = 1536 f4
    float4* w_ih1 = w_hh0 + 12 * WH_S;
    float4* w_hh1 = w_ih1 + 12 * WH_S;
    float4* tiles = w_hh1 + 12 * WH_S;                  // 2 x 2112 f4
    __shared__ float pool_sh[32];
    __shared__ int   tok_sh[BATCH];

    const int tid = threadIdx.x;
    const int bid = blockIdx.x;
    const int j0  = bid * 4;
    const int kq  = tid & 7;           // lane bits 0-2: K-slice
    const int jj  = (tid >> 3) & 3;    // lane bits 3-4: unit
    const int bg  = tid >> 5;          // warp id: batch group (8 batches)
    const int j   = j0 + jj;
    const int b0  = bg * 8;

    // ---- stage weights (once) ----
    for (int idx = tid; idx < 12 * WIH0_S; idx += NTHREADS) {
        int m = idx / WIH0_S, f4 = idx - m * WIH0_S;
        int g = m >> 2, u = m & 3;
        float4 v = make_float4(0.f, 0.f, 0.f, 0.f);
        if (f4 < 75)
            v = reinterpret_cast<const float4*>(Wih0 + (size_t)(g * HDIM + j0 + u) * EDIM)[f4];
        w_ih0[idx] = v;
    }
    stage128(w_hh0, Whh0, j0, tid);
    stage128(w_ih1, Wih1, j0, tid);
    stage128(w_hh1, Whh1, j0, tid);

    const float br0 = bih0[j] + bhh0[j];
    const float bz0 = bih0[HDIM + j] + bhh0[HDIM + j];
    const float bx0 = bih0[2 * HDIM + j];
    const float bh0 = bhh0[2 * HDIM + j];
    const float br1 = bih1[j] + bhh1[j];
    const float bz1 = bih1[HDIM + j] + bhh1[HDIM + j];
    const float bx1 = bih1[2 * HDIM + j];
    const float bh1 = bhh1[2 * HDIM + j];

    // per-thread weight row pointers (1 ull2 == 1 f4), +kq base; chunk +32 f4
    const ulonglong2* eR  = (const ulonglong2*)w_ih0 + (0 + jj) * WIH0_S + kq;
    const ulonglong2* eZ  = (const ulonglong2*)w_ih0 + (4 + jj) * WIH0_S + kq;
    const ulonglong2* eN  = (const ulonglong2*)w_ih0 + (8 + jj) * WIH0_S + kq;
    const ulonglong2* hR0 = (const ulonglong2*)w_hh0 + (0 + jj) * WH_S + kq;
    const ulonglong2* hZ0 = (const ulonglong2*)w_hh0 + (4 + jj) * WH_S + kq;
    const ulonglong2* hN0 = (const ulonglong2*)w_hh0 + (8 + jj) * WH_S + kq;
    const ulonglong2* xR1 = (const ulonglong2*)w_ih1 + (0 + jj) * WH_S + kq;
    const ulonglong2* xZ1 = (const ulonglong2*)w_ih1 + (4 + jj) * WH_S + kq;
    const ulonglong2* xN1 = (const ulonglong2*)w_ih1 + (8 + jj) * WH_S + kq;
    const ulonglong2* hR1 = (const ulonglong2*)w_hh1 + (0 + jj) * WH_S + kq;
    const ulonglong2* hZ1 = (const ulonglong2*)w_hh1 + (4 + jj) * WH_S + kq;
    const ulonglong2* hN1 = (const ulonglong2*)w_hh1 + (8 + jj) * WH_S + kq;

    const uint32_t tile_u32_0 = (uint32_t)__cvta_generic_to_shared(tiles);
    const uint32_t tile_u32_1 = (uint32_t)__cvta_generic_to_shared(tiles + TILE_F4);
    const float4* emb4 = (const float4*)emb;

#define DSTU32(QI, I) (((QI) & 1 ? tile_u32_1 : tile_u32_0) +                     \
        ((((tid + (I) * NTHREADS) >> 5) * TILE_S + ((tid + (I) * NTHREADS) & 31)) << 4))
#define STAGE_EMB(CC, QI) do { int c_ = (CC);                                    \
    _Pragma("unroll") for (int i = 0; i < 8; i++) {                              \
        int idx = tid + i * NTHREADS; int rr = idx >> 5, f4 = idx & 31;          \
        int gf4 = c_ * 32 + f4;                                                  \
        const float4* sp = emb4 + (size_t)tok_sh[rr] * 75 + (gf4 < 75 ? gf4 : 0);\
        cp16(DSTU32(QI, i), sp, gf4 < 75 ? 16u : 0u); }                          \
    cp_commit(); } while (0)
#define STAGE_H(SRC4, CC, QI) do { int c_ = (CC);                                \
    _Pragma("unroll") for (int i = 0; i < 8; i++) {                              \
        int idx = tid + i * NTHREADS; int rr = idx >> 5, f4 = idx & 31;          \
        cp16(DSTU32(QI, i), (SRC4) + rr * 128 + c_ * 32 + f4, 16u); }            \
    cp_commit(); } while (0)
#define CHUNK_READY() do { cp_wait0(); __syncthreads(); } while (0)
#define TPTR(QI) ((const ulonglong2*)(tiles + ((QI) & 1) * TILE_F4) + b0 * TILE_S + kq)

    for (int s = 0; s <= T_STEPS + 1; s++) {
        const bool do0 = (s < T_STEPS);
        const int  t1  = s - 2;                        // layer1 time index
        const bool do1 = (t1 >= 0);
        const float*  h1prev  = (s == 0) ? g_zero : g_h1 + (size_t)(s - 1) * BH;
        const float4* h1prev4 = (const float4*)h1prev;
        const float4* h1in4   = (const float4*)(do1 ? (g_h1 + (size_t)t1 * BH) : g_zero);
        const float*  h2prev  = (t1 <= 0) ? g_zero : g_h2 + (size_t)(t1 - 1) * BH;
        const float4* h2prev4 = (const float4*)h2prev;

        if (do0 && tid < BATCH) tok_sh[tid] = texts[s * BATCH + tid];
        __syncthreads();     // tok visible; closes last step's tile/pool use

        ull AR[8], AZ[8], AX[8];
        ull BR[8], BZ[8], BX[8];
#pragma unroll
        for (int i = 0; i < 8; i++) {
            AR[i] = AZ[i] = AX[i] = 0ull;
            BR[i] = BZ[i] = BX[i] = 0ull;
        }

        int qi = 0;

        // ---- pre-wait: L0 embedding projection ----
        if (do0) {
            STAGE_EMB(0, qi);
            for (int c = 0; c < 3; c++) {
                CHUNK_READY();
                if (c < 2)     STAGE_EMB(c + 1, qi + 1);
                else if (do1)  STAGE_H(h1in4, 0, qi + 1);
                mac3x8(TPTR(qi), eR + c * 32, eZ + c * 32, eN + c * 32, AR, AZ, AX);
                qi++;
            }
        } else if (do1) {
            STAGE_H(h1in4, 0, qi);
        }

        // ---- pre-wait: L1 input projection from h1[s-2] (published 2 steps ago) ----
        if (do1) {
            for (int c = 0; c < 4; c++) {
                CHUNK_READY();
                if (c < 3) STAGE_H(h1in4, c + 1, qi + 1);
                mac3x8(TPTR(qi), xR1 + c * 32, xZ1 + c * 32, xN1 + c * 32, BR, BZ, BX);
                qi++;
            }
        }

        // ---- grid wait (aggregator): all CTAs finished step s-1 ----
        if (s > 0) {
            if (bid == 0) {
                if (tid < NBLK) {
                    while (*(volatile unsigned*)&g_flags[tid] < (unsigned)s) { }
                }
                __syncthreads();
                if (tid == 0) *(volatile unsigned*)&g_release = (unsigned)s;
            } else {
                if (tid == 0) {
                    while (*(volatile unsigned*)&g_release < (unsigned)s) { }
                }
            }
            __syncthreads();
            __threadfence();     // acquire
        }

        // ---- post-wait: L0 recurrent from h1[s-1] ----
        ull AH[8];
#pragma unroll
        for (int i = 0; i < 8; i++) AH[i] = 0ull;
        if (do0) {
            STAGE_H(h1prev4, 0, qi);
            for (int c = 0; c < 4; c++) {
                CHUNK_READY();
                if (c < 3)     STAGE_H(h1prev4, c + 1, qi + 1);
                else if (do1)  STAGE_H(h2prev4, 0, qi + 1);
                mac3x8(TPTR(qi), hR0 + c * 32, hZ0 + c * 32, hN0 + c * 32, AR, AZ, AH);
                qi++;
            }
            // retire layer0 now (frees A accs)
#pragma unroll
            for (int i = 0; i < 8; i++) {
                float fr = redq(AR[i]);
                float fz = redq(AZ[i]);
                float fx = redq(AX[i]);
                float fh = redq(AH[i]);
                if (kq == 0) {
                    int b = b0 + i;
                    float r = sigf(fr + br0);
                    float z = sigf(fz + bz0);
                    float n = tanhf(fx + bx0 + r * (fh + bh0));
                    float hp = h1prev[b * HDIM + j];
                    g_h1[(size_t)s * BH + b * HDIM + j] = (1.0f - z) * n + z * hp;
                }
            }
        } else if (do1) {
            STAGE_H(h2prev4, 0, qi);
        }

        // ---- post-wait: L1 recurrent from h2[s-3] ----
        if (do1) {
            ull BHa[8];
#pragma unroll
            for (int i = 0; i < 8; i++) BHa[i] = 0ull;
            for (int c = 0; c < 4; c++) {
                CHUNK_READY();
                if (c < 3) STAGE_H(h2prev4, c + 1, qi + 1);
                mac3x8(TPTR(qi), hR1 + c * 32, hZ1 + c * 32, hN1 + c * 32, BR, BZ, BHa);
                qi++;
            }

            float psum = 0.f;
#pragma unroll
            for (int i = 0; i < 8; i++) {
                float fr = redq(BR[i]);
                float fz = redq(BZ[i]);
                float fx = redq(BX[i]);
                float fh = redq(BHa[i]);
                if (kq == 0) {
                    int b = b0 + i;
                    float r = sigf(fr + br1);
                    float z = sigf(fz + bz1);
                    float n = tanhf(fx + bx1 + r * (fh + bh1));
                    float hp = h2prev[b * HDIM + j];
                    float hnew = (1.0f - z) * n + z * hp;
                    g_h2[(size_t)t1 * BH + b * HDIM + j] = hnew;
                    psum += hnew;
                }
            }
            if (kq == 0) pool_sh[bg * 4 + jj] = psum;   // 32 slots
            __syncthreads();
            if (tid < 4) {
                float sum = 0.f;
#pragma unroll
                for (int g = 0; g < 8; g++) sum += pool_sh[g * 4 + tid];
                g_pooled[t1 * HDIM + j0 + tid] = sum * (1.0f / BATCH);
            }
        }

        // ---- arrive: publish end of step s (absolute value s+1) ----
        __threadfence();
        __syncthreads();
        if (tid == 0)
            *(volatile unsigned*)&g_flags[bid] = (unsigned)(s + 1);
    }

    // ---- epilogue: CTA 0 resets barrier state for the next graph replay ----
    if (bid == 0) {
        if (tid < NBLK) {
            while (*(volatile unsigned*)&g_flags[tid] < (unsigned)(T_STEPS + 2)) { }
        }
        __syncthreads();
        if (tid < NBLK) *(volatile unsigned*)&g_flags[tid] = 0u;
        if (tid == 0)   *(volatile unsigned*)&g_release   = 0u;
    }
#undef DSTU32
#undef STAGE_EMB
#undef STAGE_H
#undef CHUNK_READY
#undef TPTR
}

// =====================  final FC: [T,H] @ [L,H]^T + b  ======================
__global__ void fc_kernel(const float* __restrict__ fcW, const float* __restrict__ fcb,
                          float* __restrict__ out)
{
    int t    = blockIdx.x;
    int l    = threadIdx.x >> 5;   // 5 warps -> 5 outputs
    int lane = threadIdx.x & 31;
    const float* p = g_pooled + t * HDIM;
    const float* w = fcW + l * HDIM;
    float s = 0.f;
#pragma unroll 4
    for (int k = lane; k < HDIM; k += 32) s += p[k] * w[k];
#pragma unroll
    for (int o = 16; o; o >>= 1) s += __shfl_xor_sync(0xffffffffu, s, o);
    if (lane == 0) out[t * 5 + l] = s + fcb[l];
}

// ===========================================================================
extern "C" void kernel_launch(void* const* d_in, const int* in_sizes, int n_in,
                              void* d_out, int out_size) {
    (void)in_sizes; (void)n_in; (void)out_size;
    const int*   texts = (const int*)  d_in[0];
    const float* emb   = (const float*)d_in[1];
    const float* Wih0  = (const float*)d_in[2];
    const float* Whh0  = (const float*)d_in[3];
    const float* bih0  = (const float*)d_in[4];
    const float* bhh0  = (const float*)d_in[5];
    const float* Wih1  = (const float*)d_in[6];
    const float* Whh1  = (const float*)d_in[7];
    const float* bih1  = (const float*)d_in[8];
    const float* bhh1  = (const float*)d_in[9];
    const float* fcW   = (const float*)d_in[10];
    const float* fcb   = (const float*)d_in[11];
    float* out = (float*)d_out;

    // 1152 + 3*1536 + 2*2112 = 9984 float4 = 159,744 B dynamic SMEM
    const int smemB = (12 * WIH0_S + 3 * 12 * WH_S + 2 * TILE_F4) * 16;
    cudaFuncSetAttribute(gru_fused, cudaFuncAttributeMaxDynamicSharedMemorySize, smemB);

    gru_fused<<<NBLK, NTHREADS, smemB>>>(texts, emb,
                                         Wih0, Whh0, bih0, bhh0,
                                         Wih1, Whh1, bih1, bhh1);
    fc_kernel<<<T_STEPS, 160>>>(fcW, fcb, out);
}